// round 2
// baseline (speedup 1.0000x reference)
#include <cuda_runtime.h>

// Problem constants
#define BB 64
#define SS 129
#define FF 768
#define DD 4
#define KDIM (SS*FF)        // 99072
#define N3 (3*BB)           // 192
#define MOM 0.9f
#define EPSV 1e-6f

// Output offsets (tuple flattened in order)
#define XMIX_N (BB*SS*FF)           // 6340608
#define LOSS_OFF XMIX_N
#define NM_OFF (XMIX_N + 1)
#define NV_OFF (NM_OFF + DD*FF)

// Gram GEMM config
#define BM 64
#define BK 16
#define KSPLIT 48
#define STEPS (KDIM/(BK*KSPLIT))    // 129
#define CHUNK (BK*STEPS)            // 2064
#define NPAIR 6

// ---------------- device scratch (static, no runtime alloc) ----------------
__device__ __align__(16) float g_sumb[BB*FF];
__device__ __align__(16) float g_sumsqb[BB*FF];
__device__ __align__(16) float g_mu[BB*FF];
__device__ __align__(16) float g_inv[BB*FF];
__device__ __align__(16) float g_nm[DD*FF];
__device__ __align__(16) float g_nsd[DD*FF];
__device__ __align__(16) float g_hg[BB*SS*FF];                 // ~25.4 MB
__device__ __align__(16) float g_gpart[NPAIR*KSPLIT*BM*BM];    // ~4.7 MB
__device__ __align__(16) float g_G[N3*N3];

// ---------------- stage A: per-(b,f) sums over S + instance-norm stats ------
__global__ void stageA(const float* __restrict__ x) {
    int b = blockIdx.x / 3;
    int f = (blockIdx.x % 3) * 256 + threadIdx.x;
    const float* p = x + (size_t)b * KDIM + f;
    float s = 0.f, s2 = 0.f;
    #pragma unroll 4
    for (int ss = 0; ss < SS; ss++) {
        float v = p[(size_t)ss * FF];
        s += v;
        s2 += v * v;
    }
    int o = b * FF + f;
    g_sumb[o] = s;
    g_sumsqb[o] = s2;
    float mu = s / (float)SS;
    float var = (s2 - (float)SS * mu * mu) / (float)(SS - 1);
    g_mu[o] = mu;
    g_inv[o] = rsqrtf(var + EPSV);
}

// ---------------- stage B: per-domain EMA mean/var --------------------------
__global__ void stageB(const float* __restrict__ mean_buf,
                       const float* __restrict__ var_buf,
                       const int* __restrict__ domain,
                       float* __restrict__ out) {
    int idx = blockIdx.x * 256 + threadIdx.x;
    if (idx >= DD * FF) return;
    int d = idx / FF, f = idx % FF;
    float s1 = 0.f, s2 = 0.f;
    int nb = 0;
    for (int b = 0; b < BB; b++) {
        if (domain[b] == d) {
            nb++;
            s1 += g_sumb[b * FF + f];
            s2 += g_sumsqb[b * FF + f];
        }
    }
    float n = (float)nb * (float)SS;
    float mu = s1 / fmaxf(n, 1.f);
    float var = (s2 - n * mu * mu) / fmaxf(n - 1.f, 1.f);
    float nm, nv;
    if (nb > 0) {
        nm = MOM * mean_buf[idx] + (1.f - MOM) * mu;
        nv = MOM * var_buf[idx] + (1.f - MOM) * var;
    } else {
        nm = mean_buf[idx];
        nv = var_buf[idx];
    }
    out[NM_OFF + idx] = nm;
    out[NV_OFF + idx] = nv;
    g_nm[idx] = nm;
    g_nsd[idx] = sqrtf(nv + EPSV);
}

// ---------------- stage C: x_mix (to out) and hg (to scratch) ---------------
__global__ void stageC(const float* __restrict__ x,
                       const float* __restrict__ lmda,
                       const float* __restrict__ hgn,
                       const int* __restrict__ domain,
                       const int* __restrict__ drand,
                       float* __restrict__ out) {
    int idx = blockIdx.x * 256 + threadIdx.x;
    if (idx >= BB * SS * FF) return;
    int b = idx / KDIM;
    int f = idx % FF;
    float xv = x[idx];
    float xn = (xv - g_mu[b * FF + f]) * g_inv[b * FF + f];
    int dom = domain[b];
    int ds = (dom + drand[b]) % DD;
    float xnew = xn * g_nsd[ds * FF + f] + g_nm[ds * FF + f];
    float l = lmda[b];
    out[idx] = l * xv + (1.f - l) * xnew;
    g_hg[idx] = g_nm[dom * FF + f] + g_nsd[dom * FF + f] * hgn[idx];
}

// ---------------- Gram matrix: G = XE * XE^T (symmetric, split-K) -----------
__device__ __forceinline__ const float* xe_row(int i, const float* x, const float* xmix) {
    if (i < BB)     return x    + (size_t)i * KDIM;
    if (i < 2*BB)   return xmix + (size_t)(i - BB) * KDIM;
    return g_hg + (size_t)(i - 2*BB) * KDIM;
}

__global__ void gramk(const float* __restrict__ x, const float* __restrict__ xmix) {
    __shared__ __align__(16) float As[BK][BM];
    __shared__ __align__(16) float Bs[BK][BM];
    const int TI[6] = {0,0,0,1,1,2};
    const int TJ[6] = {0,1,2,1,2,2};
    int pair = blockIdx.x;        // 0..5 (upper-triangular tile pairs)
    int ks   = blockIdx.y;        // 0..KSPLIT-1
    int ti = TI[pair], tj = TJ[pair];
    int t = threadIdx.x;          // 256 threads
    int lm = t >> 2, kq = t & 3;  // loader mapping: row lm, quad kq
    const float* pa = xe_row(ti * BM + lm, x, xmix) + (size_t)ks * CHUNK + kq * 4;
    const float* pb = xe_row(tj * BM + lm, x, xmix) + (size_t)ks * CHUNK + kq * 4;
    int ty = t >> 4, tx = t & 15; // compute mapping: 16x16 threads, 4x4 micro-tile
    float acc[4][4] = {};

    for (int s = 0; s < STEPS; s++) {
        float4 a4 = *(const float4*)pa;
        float4 b4 = *(const float4*)pb;
        __syncthreads();
        As[kq*4+0][lm] = a4.x; As[kq*4+1][lm] = a4.y;
        As[kq*4+2][lm] = a4.z; As[kq*4+3][lm] = a4.w;
        Bs[kq*4+0][lm] = b4.x; Bs[kq*4+1][lm] = b4.y;
        Bs[kq*4+2][lm] = b4.z; Bs[kq*4+3][lm] = b4.w;
        __syncthreads();
        #pragma unroll
        for (int k = 0; k < BK; k++) {
            float4 av = *(const float4*)&As[k][ty*4];
            float4 bv = *(const float4*)&Bs[k][tx*4];
            acc[0][0] += av.x*bv.x; acc[0][1] += av.x*bv.y; acc[0][2] += av.x*bv.z; acc[0][3] += av.x*bv.w;
            acc[1][0] += av.y*bv.x; acc[1][1] += av.y*bv.y; acc[1][2] += av.y*bv.z; acc[1][3] += av.y*bv.w;
            acc[2][0] += av.z*bv.x; acc[2][1] += av.z*bv.y; acc[2][2] += av.z*bv.z; acc[2][3] += av.z*bv.w;
            acc[3][0] += av.w*bv.x; acc[3][1] += av.w*bv.y; acc[3][2] += av.w*bv.z; acc[3][3] += av.w*bv.w;
        }
        pa += BK;
        pb += BK;
    }

    float* dst = g_gpart + ((size_t)pair * KSPLIT + ks) * (BM * BM);
    #pragma unroll
    for (int ii = 0; ii < 4; ii++)
        #pragma unroll
        for (int jj = 0; jj < 4; jj++)
            dst[(ty*4+ii) * BM + tx*4+jj] = acc[ii][jj];
}

// ---------------- deterministic split-K reduction + symmetry mirror ---------
__global__ void reduceG() {
    int idx = blockIdx.x * 256 + threadIdx.x;
    if (idx >= N3 * N3) return;
    int i = idx / N3, j = idx % N3;
    int ti = i >> 6, tj = j >> 6, li = i & 63, lj = j & 63;
    int a, b2, la, lb;
    if (ti <= tj) { a = ti; b2 = tj; la = li; lb = lj; }
    else          { a = tj; b2 = ti; la = lj; lb = li; }
    int pair = a * (5 - a) / 2 + b2;
    const float* src = g_gpart + (size_t)pair * KSPLIT * (BM * BM) + la * BM + lb;
    float sum = 0.f;
    #pragma unroll 8
    for (int ks = 0; ks < KSPLIT; ks++) sum += src[(size_t)ks * BM * BM];
    g_G[idx] = sum;
}

// ---------------- triplet-hard loss over 192x192 ----------------------------
__global__ void lossk(const int* __restrict__ labels, float* __restrict__ out) {
    __shared__ float red[256];
    int i = threadIdx.x;
    float val = 0.f;
    if (i < N3) {
        int li = (i < 2*BB) ? labels[i & 63] : -1;
        float sqi = g_G[i * N3 + i];
        float ap = -1e30f, an = 1e30f;
        for (int j = 0; j < N3; j++) {
            int lj = (j < 2*BB) ? labels[j & 63] : -1;
            float d2 = sqi + g_G[j * N3 + j] - 2.f * g_G[i * N3 + j];
            float dd = sqrtf(fmaxf(d2, 1e-12f));
            if (li == lj) ap = fmaxf(ap, dd);
            else          an = fminf(an, dd);
        }
        float z = ap - an;
        val = (z > 0.f) ? (z + log1pf(expf(-z))) : log1pf(expf(z));
    }
    red[threadIdx.x] = val;
    __syncthreads();
    for (int st = 128; st > 0; st >>= 1) {
        if (threadIdx.x < st) red[threadIdx.x] += red[threadIdx.x + st];
        __syncthreads();
    }
    if (threadIdx.x == 0) out[LOSS_OFF] = red[0] / (float)N3;
}

// ---------------- launch ----------------------------------------------------
extern "C" void kernel_launch(void* const* d_in, const int* in_sizes, int n_in,
                              void* d_out, int out_size) {
    const float* x        = (const float*)d_in[0];
    const float* lmda     = (const float*)d_in[1];
    const float* mean_buf = (const float*)d_in[2];
    const float* var_buf  = (const float*)d_in[3];
    const float* hgn      = (const float*)d_in[4];
    const int*   labels   = (const int*)d_in[5];
    const int*   domain   = (const int*)d_in[6];
    const int*   d_rand   = (const int*)d_in[7];
    float* out = (float*)d_out;

    stageA<<<BB * 3, 256>>>(x);
    stageB<<<(DD * FF + 255) / 256, 256>>>(mean_buf, var_buf, domain, out);
    stageC<<<(BB * SS * FF + 255) / 256, 256>>>(x, lmda, hgn, domain, d_rand, out);
    dim3 gg(NPAIR, KSPLIT);
    gramk<<<gg, 256>>>(x, out);
    reduceG<<<(N3 * N3 + 255) / 256, 256>>>();
    lossk<<<1, 256>>>(labels, out);
}

// round 3
// speedup vs baseline: 1.0028x; 1.0028x over previous
#include <cuda_runtime.h>

// Problem constants
#define BB 64
#define SS 129
#define FF 768
#define DD 4
#define KDIM (SS*FF)        // 99072
#define N3 (3*BB)           // 192
#define MOM 0.9f
#define EPSV 1e-6f

// Output offsets (tuple flattened in order)
#define XMIX_N (BB*SS*FF)           // 6340608
#define LOSS_OFF XMIX_N
#define NM_OFF (XMIX_N + 1)
#define NV_OFF (NM_OFF + DD*FF)

// Gram GEMM config
#define BM 64
#define BK 16
#define KSPLIT 48
#define STEPS (KDIM/(BK*KSPLIT))    // 129
#define CHUNK (BK*STEPS)            // 2064
#define NPAIR 6

// ---------------- device scratch (static, no runtime alloc) ----------------
__device__ __align__(16) float g_sumb[BB*FF];
__device__ __align__(16) float g_sumsqb[BB*FF];
__device__ __align__(16) float g_mu[BB*FF];
__device__ __align__(16) float g_inv[BB*FF];
__device__ __align__(16) float g_nm[DD*FF];
__device__ __align__(16) float g_nsd[DD*FF];
__device__ __align__(16) float g_hg[BB*SS*FF];                 // ~25.4 MB
__device__ __align__(16) float g_gpart[NPAIR*KSPLIT*BM*BM];    // ~4.7 MB
__device__ __align__(16) float g_G[N3*N3];

// ---------------- stage A: per-(b,f) sums over S + instance-norm stats ------
__global__ void stageA(const float* __restrict__ x) {
    int b = blockIdx.x / 3;
    int f = (blockIdx.x % 3) * 256 + threadIdx.x;
    const float* p = x + (size_t)b * KDIM + f;
    float s = 0.f, s2 = 0.f;
    #pragma unroll 4
    for (int ss = 0; ss < SS; ss++) {
        float v = p[(size_t)ss * FF];
        s += v;
        s2 += v * v;
    }
    int o = b * FF + f;
    g_sumb[o] = s;
    g_sumsqb[o] = s2;
    float mu = s / (float)SS;
    float var = (s2 - (float)SS * mu * mu) / (float)(SS - 1);
    g_mu[o] = mu;
    g_inv[o] = rsqrtf(var + EPSV);
}

// ---------------- stage B: per-domain EMA mean/var --------------------------
__global__ void stageB(const float* __restrict__ mean_buf,
                       const float* __restrict__ var_buf,
                       const int* __restrict__ domain,
                       float* __restrict__ out) {
    int idx = blockIdx.x * 256 + threadIdx.x;
    if (idx >= DD * FF) return;
    int d = idx / FF, f = idx % FF;
    float s1 = 0.f, s2 = 0.f;
    int nb = 0;
    for (int b = 0; b < BB; b++) {
        if (domain[b] == d) {
            nb++;
            s1 += g_sumb[b * FF + f];
            s2 += g_sumsqb[b * FF + f];
        }
    }
    float n = (float)nb * (float)SS;
    float mu = s1 / fmaxf(n, 1.f);
    float var = (s2 - n * mu * mu) / fmaxf(n - 1.f, 1.f);
    float nm, nv;
    if (nb > 0) {
        nm = MOM * mean_buf[idx] + (1.f - MOM) * mu;
        nv = MOM * var_buf[idx] + (1.f - MOM) * var;
    } else {
        nm = mean_buf[idx];
        nv = var_buf[idx];
    }
    out[NM_OFF + idx] = nm;
    out[NV_OFF + idx] = nv;
    g_nm[idx] = nm;
    g_nsd[idx] = sqrtf(nv + EPSV);
}

// ---------------- stage C: x_mix (to out) and hg (to scratch) ---------------
__global__ void stageC(const float* __restrict__ x,
                       const float* __restrict__ lmda,
                       const float* __restrict__ hgn,
                       const int* __restrict__ domain,
                       const int* __restrict__ drand,
                       float* __restrict__ out) {
    int idx = blockIdx.x * 256 + threadIdx.x;
    if (idx >= BB * SS * FF) return;
    int b = idx / KDIM;
    int f = idx % FF;
    float xv = x[idx];
    float xn = (xv - g_mu[b * FF + f]) * g_inv[b * FF + f];
    int dom = domain[b];
    int ds = (dom + drand[b]) % DD;
    float xnew = xn * g_nsd[ds * FF + f] + g_nm[ds * FF + f];
    float l = lmda[b];
    out[idx] = l * xv + (1.f - l) * xnew;
    g_hg[idx] = g_nm[dom * FF + f] + g_nsd[dom * FF + f] * hgn[idx];
}

// ---------------- Gram matrix: G = XE * XE^T (symmetric, split-K) -----------
__device__ __forceinline__ const float* xe_row(int i, const float* x, const float* xmix) {
    if (i < BB)     return x    + (size_t)i * KDIM;
    if (i < 2*BB)   return xmix + (size_t)(i - BB) * KDIM;
    return g_hg + (size_t)(i - 2*BB) * KDIM;
}

__global__ void gramk(const float* __restrict__ x, const float* __restrict__ xmix) {
    __shared__ __align__(16) float As[BK][BM];
    __shared__ __align__(16) float Bs[BK][BM];
    const int TI[6] = {0,0,0,1,1,2};
    const int TJ[6] = {0,1,2,1,2,2};
    int pair = blockIdx.x;        // 0..5 (upper-triangular tile pairs)
    int ks   = blockIdx.y;        // 0..KSPLIT-1
    int ti = TI[pair], tj = TJ[pair];
    int t = threadIdx.x;          // 256 threads
    int lm = t >> 2, kq = t & 3;  // loader mapping: row lm, quad kq
    const float* pa = xe_row(ti * BM + lm, x, xmix) + (size_t)ks * CHUNK + kq * 4;
    const float* pb = xe_row(tj * BM + lm, x, xmix) + (size_t)ks * CHUNK + kq * 4;
    int ty = t >> 4, tx = t & 15; // compute mapping: 16x16 threads, 4x4 micro-tile
    float acc[4][4] = {};

    for (int s = 0; s < STEPS; s++) {
        float4 a4 = *(const float4*)pa;
        float4 b4 = *(const float4*)pb;
        __syncthreads();
        As[kq*4+0][lm] = a4.x; As[kq*4+1][lm] = a4.y;
        As[kq*4+2][lm] = a4.z; As[kq*4+3][lm] = a4.w;
        Bs[kq*4+0][lm] = b4.x; Bs[kq*4+1][lm] = b4.y;
        Bs[kq*4+2][lm] = b4.z; Bs[kq*4+3][lm] = b4.w;
        __syncthreads();
        #pragma unroll
        for (int k = 0; k < BK; k++) {
            float4 av = *(const float4*)&As[k][ty*4];
            float4 bv = *(const float4*)&Bs[k][tx*4];
            acc[0][0] += av.x*bv.x; acc[0][1] += av.x*bv.y; acc[0][2] += av.x*bv.z; acc[0][3] += av.x*bv.w;
            acc[1][0] += av.y*bv.x; acc[1][1] += av.y*bv.y; acc[1][2] += av.y*bv.z; acc[1][3] += av.y*bv.w;
            acc[2][0] += av.z*bv.x; acc[2][1] += av.z*bv.y; acc[2][2] += av.z*bv.z; acc[2][3] += av.z*bv.w;
            acc[3][0] += av.w*bv.x; acc[3][1] += av.w*bv.y; acc[3][2] += av.w*bv.z; acc[3][3] += av.w*bv.w;
        }
        pa += BK;
        pb += BK;
    }

    float* dst = g_gpart + ((size_t)pair * KSPLIT + ks) * (BM * BM);
    #pragma unroll
    for (int ii = 0; ii < 4; ii++)
        #pragma unroll
        for (int jj = 0; jj < 4; jj++)
            dst[(ty*4+ii) * BM + tx*4+jj] = acc[ii][jj];
}

// ---------------- deterministic split-K reduction + symmetry mirror ---------
__global__ void reduceG() {
    int idx = blockIdx.x * 256 + threadIdx.x;
    if (idx >= N3 * N3) return;
    int i = idx / N3, j = idx % N3;
    int ti = i >> 6, tj = j >> 6, li = i & 63, lj = j & 63;
    int a, b2, la, lb;
    if (ti <= tj) { a = ti; b2 = tj; la = li; lb = lj; }
    else          { a = tj; b2 = ti; la = lj; lb = li; }
    int pair = a * (5 - a) / 2 + b2;
    const float* src = g_gpart + (size_t)pair * KSPLIT * (BM * BM) + la * BM + lb;
    float sum = 0.f;
    #pragma unroll 8
    for (int ks = 0; ks < KSPLIT; ks++) sum += src[(size_t)ks * BM * BM];
    g_G[idx] = sum;
}

// ---------------- triplet-hard loss over 192x192 ----------------------------
__global__ void lossk(const int* __restrict__ labels, float* __restrict__ out) {
    __shared__ float red[256];
    int i = threadIdx.x;
    float val = 0.f;
    if (i < N3) {
        int li = (i < 2*BB) ? labels[i & 63] : -1;
        float sqi = g_G[i * N3 + i];
        float ap = -1e30f, an = 1e30f;
        for (int j = 0; j < N3; j++) {
            int lj = (j < 2*BB) ? labels[j & 63] : -1;
            float d2 = sqi + g_G[j * N3 + j] - 2.f * g_G[i * N3 + j];
            float dd = sqrtf(fmaxf(d2, 1e-12f));
            if (li == lj) ap = fmaxf(ap, dd);
            else          an = fminf(an, dd);
        }
        float z = ap - an;
        val = (z > 0.f) ? (z + log1pf(expf(-z))) : log1pf(expf(z));
    }
    red[threadIdx.x] = val;
    __syncthreads();
    for (int st = 128; st > 0; st >>= 1) {
        if (threadIdx.x < st) red[threadIdx.x] += red[threadIdx.x + st];
        __syncthreads();
    }
    if (threadIdx.x == 0) out[LOSS_OFF] = red[0] / (float)N3;
}

// ---------------- launch ----------------------------------------------------
extern "C" void kernel_launch(void* const* d_in, const int* in_sizes, int n_in,
                              void* d_out, int out_size) {
    const float* x        = (const float*)d_in[0];
    const float* lmda     = (const float*)d_in[1];
    const float* mean_buf = (const float*)d_in[2];
    const float* var_buf  = (const float*)d_in[3];
    const float* hgn      = (const float*)d_in[4];
    const int*   labels   = (const int*)d_in[5];
    const int*   domain   = (const int*)d_in[6];
    const int*   d_rand   = (const int*)d_in[7];
    float* out = (float*)d_out;

    stageA<<<BB * 3, 256>>>(x);
    stageB<<<(DD * FF + 255) / 256, 256>>>(mean_buf, var_buf, domain, out);
    stageC<<<(BB * SS * FF + 255) / 256, 256>>>(x, lmda, hgn, domain, d_rand, out);
    dim3 gg(NPAIR, KSPLIT);
    gramk<<<gg, 256>>>(x, out);
    reduceG<<<(N3 * N3 + 255) / 256, 256>>>();
    lossk<<<1, 256>>>(labels, out);
}

// round 5
// speedup vs baseline: 2.1671x; 2.1610x over previous
#include <cuda_runtime.h>

// ---------------- problem constants ----------------
#define BB 64
#define SS 129
#define FF 768
#define DD 4
#define KDIM (SS*FF)        // 99072
#define N3 (3*BB)           // 192
#define MOM 0.9f
#define EPSV 1e-6f

// output layout (tuple flattened)
#define XMIX_N (BB*SS*FF)
#define LOSS_OFF XMIX_N
#define NM_OFF (XMIX_N + 1)
#define NV_OFF (NM_OFF + DD*FF)

// ---------------- gram config ----------------
#define KSPLIT 129          // CTAs, one K-chunk each (one wave on 148 SMs)
#define KCHUNK 768          // K per CTA (== FF, so f-index == k-offset)
#define NTILES 24           // KCHUNK / 32
#define SROW 36             // padded SMEM row stride (floats) -> conflict-free frags
#define BUF_ELEMS (N3*SROW) // 6912
#define NPAIR 6

// ---------------- device scratch ----------------
__device__ float g_sumb[BB*FF];
__device__ float g_sumsqb[BB*FF];
__device__ float g_mu[BB*FF];
__device__ float g_inv[BB*FF];
__device__ float g_nm[DD*FF];
__device__ float g_nsd[DD*FF];
__device__ float g_gpart[KSPLIT*NPAIR*64*64];   // ~12.7 MB fp32 partials
__device__ float g_G[N3*N3];

// ---------------- helpers ----------------
__device__ __forceinline__ unsigned tf32r(float v) {
    unsigned r;
    asm("cvt.rna.tf32.f32 %0, %1;" : "=r"(r) : "f"(v));
    return r;
}

__device__ __forceinline__ void mma_tf32(float* d, const unsigned* a, const unsigned* b) {
    asm volatile("mma.sync.aligned.m16n8k8.row.col.f32.tf32.tf32.f32 "
        "{%0,%1,%2,%3},{%4,%5,%6,%7},{%8,%9},{%0,%1,%2,%3};"
        : "+f"(d[0]), "+f"(d[1]), "+f"(d[2]), "+f"(d[3])
        : "r"(a[0]), "r"(a[1]), "r"(a[2]), "r"(a[3]), "r"(b[0]), "r"(b[1]));
}

// ---------------- stage A: per-(b,f) sums over S + instance-norm stats ------
__global__ void stageA(const float* __restrict__ x) {
    int b = blockIdx.x / 3;
    int f = (blockIdx.x % 3) * 256 + threadIdx.x;
    const float* p = x + (size_t)b * KDIM + f;
    float s = 0.f, s2 = 0.f;
    #pragma unroll 4
    for (int ss = 0; ss < SS; ss++) {
        float v = p[(size_t)ss * FF];
        s += v; s2 += v * v;
    }
    int o = b * FF + f;
    g_sumb[o] = s;
    g_sumsqb[o] = s2;
    float mu = s / (float)SS;
    float var = (s2 - (float)SS * mu * mu) / (float)(SS - 1);
    g_mu[o] = mu;
    g_inv[o] = rsqrtf(var + EPSV);
}

// ---------------- stage B: per-domain EMA mean/var ---------------------------
__global__ void stageB(const float* __restrict__ mean_buf,
                       const float* __restrict__ var_buf,
                       const int* __restrict__ domain,
                       float* __restrict__ out) {
    int idx = blockIdx.x * 256 + threadIdx.x;
    if (idx >= DD * FF) return;
    int d = idx / FF, f = idx % FF;
    float s1 = 0.f, s2 = 0.f;
    int nb = 0;
    for (int b = 0; b < BB; b++) {
        if (domain[b] == d) {
            nb++;
            s1 += g_sumb[b * FF + f];
            s2 += g_sumsqb[b * FF + f];
        }
    }
    float n = (float)nb * (float)SS;
    float mu = s1 / fmaxf(n, 1.f);
    float var = (s2 - n * mu * mu) / fmaxf(n - 1.f, 1.f);
    float nm, nv;
    if (nb > 0) {
        nm = MOM * mean_buf[idx] + (1.f - MOM) * mu;
        nv = MOM * var_buf[idx] + (1.f - MOM) * var;
    } else {
        nm = mean_buf[idx];
        nv = var_buf[idx];
    }
    out[NM_OFF + idx] = nm;
    out[NV_OFF + idx] = nv;
    g_nm[idx] = nm;
    g_nsd[idx] = sqrtf(nv + EPSV);
}

// ---------------- fused gram (tf32 mma.sync) + xmix + hg --------------------
// 129 CTAs, 256 threads. Each CTA: K-chunk of 768, stages [192][32] tf32 tiles,
// computes 6 upper-triangular 64x64 pair-tiles in registers. Loader rows:
//   0-63: x  |  64-127: xmix (computed here, also written to out)  |  128-191: hg
__global__ __launch_bounds__(256, 1)
void gram_tc(const float* __restrict__ x,
             const float* __restrict__ hgn,
             const float* __restrict__ lmda,
             const int* __restrict__ domain,
             const int* __restrict__ drand,
             float* __restrict__ out) {
    extern __shared__ unsigned sbuf[];   // 2 * BUF_ELEMS
    int tid = threadIdx.x;
    int ks = blockIdx.x;
    long kbase = (long)ks * KCHUNK;

    // ---- loader setup: 6 elements/thread, element i covers rows [32i,32i+32) ----
    const float* p[6];
    int soff[6];
    #pragma unroll
    for (int i = 0; i < 6; i++) {
        int e = tid + 256 * i;
        int row = e >> 3, q = e & 7;
        const float* src;
        if (row < 128) src = x + (size_t)(row & 63) * KDIM;     // x and xmix-source
        else           src = hgn + (size_t)(row - 128) * KDIM;
        p[i] = src + kbase + q * 4;
        soff[i] = row * SROW + q * 4;
    }
    float  lmv[2];
    int    offm[2], offdx[2], offdh[2];
    float* outp[2];
    #pragma unroll
    for (int j = 0; j < 2; j++) {
        int e = tid + 256 * (2 + j);
        int row = e >> 3, q = e & 7, b = row - 64;
        lmv[j] = lmda[b];
        int ds = (domain[b] + drand[b]) & 3;
        offm[j]  = b * FF + q * 4;
        offdx[j] = ds * FF + q * 4;
        outp[j]  = out + (size_t)b * KDIM + kbase + q * 4;
    }
    #pragma unroll
    for (int j = 0; j < 2; j++) {
        int e = tid + 256 * (4 + j);
        int b = (e >> 3) - 128, q = e & 7;
        offdh[j] = domain[b] * FF + q * 4;
    }

    // ---- mma setup ----
    int wid = tid >> 5, lane = tid & 31;
    int wm = wid >> 2, wn = wid & 3;      // warp grid 2x4 over 64x64 tile
    int lr = lane >> 2, lc = lane & 3;
    const int TI[NPAIR] = {0,0,0,1,1,2};
    const int TJ[NPAIR] = {0,1,2,1,2,2};
    float acc[NPAIR][2][2][4];
    #pragma unroll
    for (int pp = 0; pp < NPAIR; pp++)
        #pragma unroll
        for (int mt = 0; mt < 2; mt++)
            #pragma unroll
            for (int nt = 0; nt < 2; nt++)
                #pragma unroll
                for (int r = 0; r < 4; r++) acc[pp][mt][nt][r] = 0.f;

    float4 v[6];
    #pragma unroll
    for (int i = 0; i < 6; i++) v[i] = *(const float4*)(p[i]);

    for (int t = 0; t < NTILES; t++) {
        unsigned* bb = sbuf + (t & 1) * BUF_ELEMS;
        int fo = t * 32;
        float4 w[6];
        w[0] = v[0]; w[1] = v[1];
        // xmix rows: compute, write to out, feed to gram
        #pragma unroll
        for (int j = 0; j < 2; j++) {
            float4 xv = v[2 + j];
            float4 mu = *(const float4*)(g_mu  + offm[j]  + fo);
            float4 iv = *(const float4*)(g_inv + offm[j]  + fo);
            float4 nm = *(const float4*)(g_nm  + offdx[j] + fo);
            float4 sd = *(const float4*)(g_nsd + offdx[j] + fo);
            float l = lmv[j], il = 1.f - l;
            float4 xm;
            xm.x = l * xv.x + il * fmaf((xv.x - mu.x) * iv.x, sd.x, nm.x);
            xm.y = l * xv.y + il * fmaf((xv.y - mu.y) * iv.y, sd.y, nm.y);
            xm.z = l * xv.z + il * fmaf((xv.z - mu.z) * iv.z, sd.z, nm.z);
            xm.w = l * xv.w + il * fmaf((xv.w - mu.w) * iv.w, sd.w, nm.w);
            *(float4*)(outp[j] + fo) = xm;
            w[2 + j] = xm;
        }
        // hg rows: new_mean[dom] + new_sd[dom] * noise
        #pragma unroll
        for (int j = 0; j < 2; j++) {
            float4 nz = v[4 + j];
            float4 nm = *(const float4*)(g_nm  + offdh[j] + fo);
            float4 sd = *(const float4*)(g_nsd + offdh[j] + fo);
            float4 hg;
            hg.x = fmaf(sd.x, nz.x, nm.x);
            hg.y = fmaf(sd.y, nz.y, nm.y);
            hg.z = fmaf(sd.z, nz.z, nm.z);
            hg.w = fmaf(sd.w, nz.w, nm.w);
            w[4 + j] = hg;
        }
        // tf32 convert + STS
        #pragma unroll
        for (int i = 0; i < 6; i++) {
            uint4 u;
            u.x = tf32r(w[i].x); u.y = tf32r(w[i].y);
            u.z = tf32r(w[i].z); u.w = tf32r(w[i].w);
            *(uint4*)(&bb[soff[i]]) = u;
        }
        // prefetch next tile
        if (t + 1 < NTILES) {
            #pragma unroll
            for (int i = 0; i < 6; i++) v[i] = *(const float4*)(p[i] + (t + 1) * 32);
        }
        __syncthreads();
        // MMA on staged tile: 4 k-steps of 8
        const unsigned* S = bb;
        #pragma unroll
        for (int kk = 0; kk < 4; kk++) {
            int k0 = kk * 8;
            unsigned af[3][2][4], bf[3][2][2];
            #pragma unroll
            for (int g = 0; g < 3; g++) {
                #pragma unroll
                for (int mt = 0; mt < 2; mt++) {
                    int r0 = g * 64 + wm * 32 + mt * 16 + lr;
                    af[g][mt][0] = S[r0 * SROW + k0 + lc];
                    af[g][mt][1] = S[(r0 + 8) * SROW + k0 + lc];
                    af[g][mt][2] = S[r0 * SROW + k0 + lc + 4];
                    af[g][mt][3] = S[(r0 + 8) * SROW + k0 + lc + 4];
                }
                #pragma unroll
                for (int nt = 0; nt < 2; nt++) {
                    int n0 = g * 64 + wn * 16 + nt * 8 + lr;
                    bf[g][nt][0] = S[n0 * SROW + k0 + lc];
                    bf[g][nt][1] = S[n0 * SROW + k0 + lc + 4];
                }
            }
            #pragma unroll
            for (int pp = 0; pp < NPAIR; pp++)
                #pragma unroll
                for (int mt = 0; mt < 2; mt++)
                    #pragma unroll
                    for (int nt = 0; nt < 2; nt++)
                        mma_tf32(acc[pp][mt][nt], af[TI[pp]][mt], bf[TJ[pp]][nt]);
        }
    }

    // ---- epilogue: write 6 pair-tile partials ----
    float* base = g_gpart + (size_t)ks * NPAIR * 4096;
    #pragma unroll
    for (int pp = 0; pp < NPAIR; pp++) {
        #pragma unroll
        for (int mt = 0; mt < 2; mt++) {
            #pragma unroll
            for (int nt = 0; nt < 2; nt++) {
                int r = wm * 32 + mt * 16 + lr;
                int c = wn * 16 + nt * 8 + lc * 2;
                float* dst = base + pp * 4096 + r * 64 + c;
                *(float2*)dst = make_float2(acc[pp][mt][nt][0], acc[pp][mt][nt][1]);
                *(float2*)(dst + 8 * 64) = make_float2(acc[pp][mt][nt][2], acc[pp][mt][nt][3]);
            }
        }
    }
}

// ---------------- deterministic split-K reduction + symmetry mirror ---------
__global__ void reduceG() {
    int idx = blockIdx.x * 256 + threadIdx.x;
    if (idx >= N3 * N3) return;
    int i = idx / N3, j = idx % N3;
    int ti = i >> 6, tj = j >> 6, li = i & 63, lj = j & 63;
    int a, b2, la, lb;
    if (ti <= tj) { a = ti; b2 = tj; la = li; lb = lj; }
    else          { a = tj; b2 = ti; la = lj; lb = li; }
    int pair = a * (5 - a) / 2 + b2;
    const float* src = g_gpart + (size_t)pair * 4096 + la * 64 + lb;
    float s0 = 0.f, s1 = 0.f, s2 = 0.f;
    const size_t stride = (size_t)NPAIR * 4096;
    #pragma unroll
    for (int p = 0; p < 129; p += 3) {
        s0 += src[(size_t)p * stride];
        s1 += src[(size_t)(p + 1) * stride];
        s2 += src[(size_t)(p + 2) * stride];
    }
    g_G[idx] = s0 + s1 + s2;
}

// ---------------- triplet-hard loss over 192x192 ----------------------------
__global__ void lossk(const int* __restrict__ labels, float* __restrict__ out) {
    __shared__ float red[256];
    int i = threadIdx.x;
    float val = 0.f;
    if (i < N3) {
        int li = (i < 2 * BB) ? labels[i & 63] : -1;
        float sqi = g_G[i * N3 + i];
        float ap = -1e30f, an = 1e30f;
        for (int j = 0; j < N3; j++) {
            int lj = (j < 2 * BB) ? labels[j & 63] : -1;
            float d2 = sqi + g_G[j * N3 + j] - 2.f * g_G[i * N3 + j];
            float dd = sqrtf(fmaxf(d2, 1e-12f));
            if (li == lj) ap = fmaxf(ap, dd);
            else          an = fminf(an, dd);
        }
        float z = ap - an;
        val = (z > 0.f) ? (z + log1pf(expf(-z))) : log1pf(expf(z));
    }
    red[threadIdx.x] = val;
    __syncthreads();
    for (int st = 128; st > 0; st >>= 1) {
        if (threadIdx.x < st) red[threadIdx.x] += red[threadIdx.x + st];
        __syncthreads();
    }
    if (threadIdx.x == 0) out[LOSS_OFF] = red[0] / (float)N3;
}

// ---------------- launch -----------------------------------------------------
extern "C" void kernel_launch(void* const* d_in, const int* in_sizes, int n_in,
                              void* d_out, int out_size) {
    const float* x        = (const float*)d_in[0];
    const float* lmda     = (const float*)d_in[1];
    const float* mean_buf = (const float*)d_in[2];
    const float* var_buf  = (const float*)d_in[3];
    const float* hgn      = (const float*)d_in[4];
    const int*   labels   = (const int*)d_in[5];
    const int*   domain   = (const int*)d_in[6];
    const int*   d_rand   = (const int*)d_in[7];
    float* out = (float*)d_out;

    int smem_sz = 2 * BUF_ELEMS * (int)sizeof(unsigned);   // 55296
    cudaFuncSetAttribute(gram_tc, cudaFuncAttributeMaxDynamicSharedMemorySize, smem_sz);

    stageA<<<BB * 3, 256>>>(x);
    stageB<<<(DD * FF + 255) / 256, 256>>>(mean_buf, var_buf, domain, out);
    gram_tc<<<KSPLIT, 256, smem_sz>>>(x, hgn, lmda, domain, d_rand, out);
    reduceG<<<(N3 * N3 + 255) / 256, 256>>>();
    lossk<<<1, 256>>>(labels, out);
}

// round 6
// speedup vs baseline: 3.5200x; 1.6243x over previous
#include <cuda_runtime.h>

// ---------------- problem constants ----------------
#define BB 64
#define SS 129
#define FF 768
#define DD 4
#define KDIM (SS*FF)        // 99072
#define N3 (3*BB)           // 192
#define MOM 0.9f
#define EPSV 1e-6f

// output layout (tuple flattened)
#define XMIX_N (BB*SS*FF)
#define LOSS_OFF XMIX_N
#define NM_OFF (XMIX_N + 1)
#define NV_OFF (NM_OFF + DD*FF)

// ---------------- gram config ----------------
#define KSPLIT 129          // CTAs, one K-chunk each (one wave on 148 SMs)
#define KCHUNK 768
#define NTILES 24
#define SROW 36
#define BUF_ELEMS (N3*SROW)
#define NPAIR 6
#define PAIRSZ 4096         // 64*64
#define KSLAB (NPAIR*PAIRSZ)   // 24576

// ---------------- device scratch ----------------
__device__ float g_pA1[4][BB*FF];
__device__ float g_pA2[4][BB*FF];
__device__ float g_sumb[BB*FF];
__device__ float g_sumsqb[BB*FF];
__device__ float g_mu[BB*FF];
__device__ float g_inv[BB*FF];
__device__ float g_nm[DD*FF];
__device__ float g_nsd[DD*FF];
__device__ float g_gpart[KSPLIT*KSLAB];   // ~12.7 MB fp32 partials
__device__ float g_part2[8][KSLAB];
__device__ float g_G[N3*N3];
__device__ float g_rowloss[N3];

// ---------------- helpers ----------------
__device__ __forceinline__ unsigned tf32r(float v) {
    unsigned r;
    asm("cvt.rna.tf32.f32 %0, %1;" : "=r"(r) : "f"(v));
    return r;
}

__device__ __forceinline__ void mma_tf32(float* d, const unsigned* a, const unsigned* b) {
    asm volatile("mma.sync.aligned.m16n8k8.row.col.f32.tf32.tf32.f32 "
        "{%0,%1,%2,%3},{%4,%5,%6,%7},{%8,%9},{%0,%1,%2,%3};"
        : "+f"(d[0]), "+f"(d[1]), "+f"(d[2]), "+f"(d[3])
        : "r"(a[0]), "r"(a[1]), "r"(a[2]), "r"(a[3]), "r"(b[0]), "r"(b[1]));
}

// ---------------- stage A1: split-S partial sums -----------------------------
__global__ void stageA1(const float* __restrict__ x) {
    int bf = blockIdx.x;               // 0..191: b = bf/3, f-chunk = bf%3
    int seg = blockIdx.y;              // 0..3
    int b = bf / 3;
    int f = (bf % 3) * 256 + threadIdx.x;
    int s0 = (seg == 0) ? 0 : 33 + 32 * (seg - 1);
    int s1 = 33 + 32 * seg;            // seg0:[0,33) seg1:[33,65) seg2:[65,97) seg3:[97,129)
    const float* p = x + (size_t)b * KDIM + f;
    float sa = 0.f, sb2 = 0.f, sc = 0.f, sd2 = 0.f;
    int ss = s0;
    for (; ss + 1 < s1; ss += 2) {
        float v0 = p[(size_t)ss * FF];
        float v1 = p[(size_t)(ss + 1) * FF];
        sa += v0; sb2 += v0 * v0;
        sc += v1; sd2 += v1 * v1;
    }
    if (ss < s1) { float v = p[(size_t)ss * FF]; sa += v; sb2 += v * v; }
    int o = b * FF + f;
    g_pA1[seg][o] = sa + sc;
    g_pA2[seg][o] = sb2 + sd2;
}

// ---------------- stage A2: combine partials, per-instance stats -------------
__global__ void stageA2() {
    int idx = blockIdx.x * 256 + threadIdx.x;   // 49152
    float s  = g_pA1[0][idx] + g_pA1[1][idx] + g_pA1[2][idx] + g_pA1[3][idx];
    float s2 = g_pA2[0][idx] + g_pA2[1][idx] + g_pA2[2][idx] + g_pA2[3][idx];
    g_sumb[idx] = s;
    g_sumsqb[idx] = s2;
    float mu = s / (float)SS;
    float var = (s2 - (float)SS * mu * mu) / (float)(SS - 1);
    g_mu[idx] = mu;
    g_inv[idx] = rsqrtf(var + EPSV);
}

// ---------------- stage B: per-domain EMA mean/var ---------------------------
__global__ void stageB(const float* __restrict__ mean_buf,
                       const float* __restrict__ var_buf,
                       const int* __restrict__ domain,
                       float* __restrict__ out) {
    int idx = blockIdx.x * 256 + threadIdx.x;
    if (idx >= DD * FF) return;
    int d = idx / FF, f = idx % FF;
    float s1 = 0.f, s2 = 0.f;
    int nb = 0;
    for (int b = 0; b < BB; b++) {
        if (domain[b] == d) {
            nb++;
            s1 += g_sumb[b * FF + f];
            s2 += g_sumsqb[b * FF + f];
        }
    }
    float n = (float)nb * (float)SS;
    float mu = s1 / fmaxf(n, 1.f);
    float var = (s2 - n * mu * mu) / fmaxf(n - 1.f, 1.f);
    float nm, nv;
    if (nb > 0) {
        nm = MOM * mean_buf[idx] + (1.f - MOM) * mu;
        nv = MOM * var_buf[idx] + (1.f - MOM) * var;
    } else {
        nm = mean_buf[idx];
        nv = var_buf[idx];
    }
    out[NM_OFF + idx] = nm;
    out[NV_OFF + idx] = nv;
    g_nm[idx] = nm;
    g_nsd[idx] = sqrtf(nv + EPSV);
}

// ---------------- fused gram (tf32 mma.sync) + xmix + hg ---------------------
__global__ __launch_bounds__(256, 1)
void gram_tc(const float* __restrict__ x,
             const float* __restrict__ hgn,
             const float* __restrict__ lmda,
             const int* __restrict__ domain,
             const int* __restrict__ drand,
             float* __restrict__ out) {
    extern __shared__ unsigned sbuf[];   // 2 * BUF_ELEMS
    int tid = threadIdx.x;
    int ks = blockIdx.x;
    long kbase = (long)ks * KCHUNK;

    const float* p[6];
    int soff[6];
    #pragma unroll
    for (int i = 0; i < 6; i++) {
        int e = tid + 256 * i;
        int row = e >> 3, q = e & 7;
        const float* src;
        if (row < 128) src = x + (size_t)(row & 63) * KDIM;
        else           src = hgn + (size_t)(row - 128) * KDIM;
        p[i] = src + kbase + q * 4;
        soff[i] = row * SROW + q * 4;
    }
    float  lmv[2];
    int    offm[2], offdx[2], offdh[2];
    float* outp[2];
    #pragma unroll
    for (int j = 0; j < 2; j++) {
        int e = tid + 256 * (2 + j);
        int row = e >> 3, q = e & 7, b = row - 64;
        lmv[j] = lmda[b];
        int ds = (domain[b] + drand[b]) & 3;
        offm[j]  = b * FF + q * 4;
        offdx[j] = ds * FF + q * 4;
        outp[j]  = out + (size_t)b * KDIM + kbase + q * 4;
    }
    #pragma unroll
    for (int j = 0; j < 2; j++) {
        int e = tid + 256 * (4 + j);
        int b = (e >> 3) - 128, q = e & 7;
        offdh[j] = domain[b] * FF + q * 4;
    }

    int wid = tid >> 5, lane = tid & 31;
    int wm = wid >> 2, wn = wid & 3;
    int lr = lane >> 2, lc = lane & 3;
    const int TI[NPAIR] = {0,0,0,1,1,2};
    const int TJ[NPAIR] = {0,1,2,1,2,2};
    float acc[NPAIR][2][2][4];
    #pragma unroll
    for (int pp = 0; pp < NPAIR; pp++)
        #pragma unroll
        for (int mt = 0; mt < 2; mt++)
            #pragma unroll
            for (int nt = 0; nt < 2; nt++)
                #pragma unroll
                for (int r = 0; r < 4; r++) acc[pp][mt][nt][r] = 0.f;

    float4 v[6];
    #pragma unroll
    for (int i = 0; i < 6; i++) v[i] = *(const float4*)(p[i]);

    for (int t = 0; t < NTILES; t++) {
        unsigned* bb = sbuf + (t & 1) * BUF_ELEMS;
        int fo = t * 32;
        float4 w[6];
        w[0] = v[0]; w[1] = v[1];
        #pragma unroll
        for (int j = 0; j < 2; j++) {
            float4 xv = v[2 + j];
            float4 mu = *(const float4*)(g_mu  + offm[j]  + fo);
            float4 iv = *(const float4*)(g_inv + offm[j]  + fo);
            float4 nm = *(const float4*)(g_nm  + offdx[j] + fo);
            float4 sd = *(const float4*)(g_nsd + offdx[j] + fo);
            float l = lmv[j], il = 1.f - l;
            float4 xm;
            xm.x = l * xv.x + il * fmaf((xv.x - mu.x) * iv.x, sd.x, nm.x);
            xm.y = l * xv.y + il * fmaf((xv.y - mu.y) * iv.y, sd.y, nm.y);
            xm.z = l * xv.z + il * fmaf((xv.z - mu.z) * iv.z, sd.z, nm.z);
            xm.w = l * xv.w + il * fmaf((xv.w - mu.w) * iv.w, sd.w, nm.w);
            *(float4*)(outp[j] + fo) = xm;
            w[2 + j] = xm;
        }
        #pragma unroll
        for (int j = 0; j < 2; j++) {
            float4 nz = v[4 + j];
            float4 nm = *(const float4*)(g_nm  + offdh[j] + fo);
            float4 sd = *(const float4*)(g_nsd + offdh[j] + fo);
            float4 hg;
            hg.x = fmaf(sd.x, nz.x, nm.x);
            hg.y = fmaf(sd.y, nz.y, nm.y);
            hg.z = fmaf(sd.z, nz.z, nm.z);
            hg.w = fmaf(sd.w, nz.w, nm.w);
            w[4 + j] = hg;
        }
        #pragma unroll
        for (int i = 0; i < 6; i++) {
            uint4 u;
            u.x = tf32r(w[i].x); u.y = tf32r(w[i].y);
            u.z = tf32r(w[i].z); u.w = tf32r(w[i].w);
            *(uint4*)(&bb[soff[i]]) = u;
        }
        if (t + 1 < NTILES) {
            #pragma unroll
            for (int i = 0; i < 6; i++) v[i] = *(const float4*)(p[i] + (t + 1) * 32);
        }
        __syncthreads();
        const unsigned* S = bb;
        #pragma unroll
        for (int kk = 0; kk < 4; kk++) {
            int k0 = kk * 8;
            unsigned af[3][2][4], bf[3][2][2];
            #pragma unroll
            for (int g = 0; g < 3; g++) {
                #pragma unroll
                for (int mt = 0; mt < 2; mt++) {
                    int r0 = g * 64 + wm * 32 + mt * 16 + lr;
                    af[g][mt][0] = S[r0 * SROW + k0 + lc];
                    af[g][mt][1] = S[(r0 + 8) * SROW + k0 + lc];
                    af[g][mt][2] = S[r0 * SROW + k0 + lc + 4];
                    af[g][mt][3] = S[(r0 + 8) * SROW + k0 + lc + 4];
                }
                #pragma unroll
                for (int nt = 0; nt < 2; nt++) {
                    int n0 = g * 64 + wn * 16 + nt * 8 + lr;
                    bf[g][nt][0] = S[n0 * SROW + k0 + lc];
                    bf[g][nt][1] = S[n0 * SROW + k0 + lc + 4];
                }
            }
            #pragma unroll
            for (int pp = 0; pp < NPAIR; pp++)
                #pragma unroll
                for (int mt = 0; mt < 2; mt++)
                    #pragma unroll
                    for (int nt = 0; nt < 2; nt++)
                        mma_tf32(acc[pp][mt][nt], af[TI[pp]][mt], bf[TJ[pp]][nt]);
        }
    }

    float* base = g_gpart + (size_t)ks * KSLAB;
    #pragma unroll
    for (int pp = 0; pp < NPAIR; pp++) {
        #pragma unroll
        for (int mt = 0; mt < 2; mt++) {
            #pragma unroll
            for (int nt = 0; nt < 2; nt++) {
                int r = wm * 32 + mt * 16 + lr;
                int c = wn * 16 + nt * 8 + lc * 2;
                float* dst = base + pp * PAIRSZ + r * 64 + c;
                *(float2*)dst = make_float2(acc[pp][mt][nt][0], acc[pp][mt][nt][1]);
                *(float2*)(dst + 8 * 64) = make_float2(acc[pp][mt][nt][2], acc[pp][mt][nt][3]);
            }
        }
    }
}

// ---------------- split-K reduction stage 1: 129 -> 8 ------------------------
__global__ void reduceG1() {
    int idx = blockIdx.x * 256 + threadIdx.x;   // 0..24575
    int c = blockIdx.y;                          // 0..7
    int p0 = c * 16;
    int p1 = (c == 7) ? 129 : p0 + 16;
    const float* src = g_gpart + (size_t)p0 * KSLAB + idx;
    float s0 = 0.f, s1 = 0.f, s2 = 0.f, s3 = 0.f;
    int n = p1 - p0;
    int p = 0;
    for (; p + 3 < n; p += 4) {
        s0 += src[(size_t)p * KSLAB];
        s1 += src[(size_t)(p + 1) * KSLAB];
        s2 += src[(size_t)(p + 2) * KSLAB];
        s3 += src[(size_t)(p + 3) * KSLAB];
    }
    for (; p < n; p++) s0 += src[(size_t)p * KSLAB];
    g_part2[c][idx] = (s0 + s1) + (s2 + s3);
}

// ---------------- stage 2: sum 8 chunks + symmetry mirror --------------------
__global__ void reduceG2() {
    int idx = blockIdx.x * 256 + threadIdx.x;
    if (idx >= N3 * N3) return;
    int i = idx / N3, j = idx % N3;
    int ti = i >> 6, tj = j >> 6, li = i & 63, lj = j & 63;
    int a, b2, la, lb;
    if (ti <= tj) { a = ti; b2 = tj; la = li; lb = lj; }
    else          { a = tj; b2 = ti; la = lj; lb = li; }
    int pair = a * (5 - a) / 2 + b2;
    int o = pair * PAIRSZ + la * 64 + lb;
    float s = 0.f;
    #pragma unroll
    for (int c = 0; c < 8; c++) s += g_part2[c][o];
    g_G[idx] = s;
}

// ---------------- triplet loss: warp per row ---------------------------------
__global__ void lossA(const int* __restrict__ labels) {
    int i = (blockIdx.x * blockDim.x + threadIdx.x) >> 5;   // 192 warps total
    int lane = threadIdx.x & 31;
    int li = (i < 2 * BB) ? labels[i & 63] : -1;
    float sqi = g_G[i * N3 + i];
    float ap = -1e30f, an = 1e30f;
    #pragma unroll
    for (int jj = 0; jj < 6; jj++) {
        int j = lane + jj * 32;
        int lj = (j < 2 * BB) ? labels[j & 63] : -1;
        float d2 = sqi + g_G[j * N3 + j] - 2.f * g_G[i * N3 + j];
        float dd = sqrtf(fmaxf(d2, 1e-12f));
        if (li == lj) ap = fmaxf(ap, dd);
        else          an = fminf(an, dd);
    }
    #pragma unroll
    for (int o = 16; o > 0; o >>= 1) {
        ap = fmaxf(ap, __shfl_xor_sync(0xFFFFFFFFu, ap, o));
        an = fminf(an, __shfl_xor_sync(0xFFFFFFFFu, an, o));
    }
    if (lane == 0) {
        float z = ap - an;
        g_rowloss[i] = (z > 0.f) ? (z + log1pf(expf(-z))) : log1pf(expf(z));
    }
}

__global__ void lossB(float* __restrict__ out) {
    __shared__ float red[256];
    int t = threadIdx.x;
    red[t] = (t < N3) ? g_rowloss[t] : 0.f;
    __syncthreads();
    for (int st = 128; st > 0; st >>= 1) {
        if (t < st) red[t] += red[t + st];
        __syncthreads();
    }
    if (t == 0) out[LOSS_OFF] = red[0] / (float)N3;
}

// ---------------- launch ------------------------------------------------------
extern "C" void kernel_launch(void* const* d_in, const int* in_sizes, int n_in,
                              void* d_out, int out_size) {
    const float* x        = (const float*)d_in[0];
    const float* lmda     = (const float*)d_in[1];
    const float* mean_buf = (const float*)d_in[2];
    const float* var_buf  = (const float*)d_in[3];
    const float* hgn      = (const float*)d_in[4];
    const int*   labels   = (const int*)d_in[5];
    const int*   domain   = (const int*)d_in[6];
    const int*   d_rand   = (const int*)d_in[7];
    float* out = (float*)d_out;

    int smem_sz = 2 * BUF_ELEMS * (int)sizeof(unsigned);   // 55296
    cudaFuncSetAttribute(gram_tc, cudaFuncAttributeMaxDynamicSharedMemorySize, smem_sz);

    dim3 ga(BB * 3, 4);
    stageA1<<<ga, 256>>>(x);
    stageA2<<<BB * FF / 256, 256>>>();
    stageB<<<(DD * FF + 255) / 256, 256>>>(mean_buf, var_buf, domain, out);
    gram_tc<<<KSPLIT, 256, smem_sz>>>(x, hgn, lmda, domain, d_rand, out);
    dim3 gr(KSLAB / 256, 8);
    reduceG1<<<gr, 256>>>();
    reduceG2<<<(N3 * N3 + 255) / 256, 256>>>();
    lossA<<<N3 / 8, 256>>>(labels);
    lossB<<<1, 256>>>(out);
}

// round 7
// speedup vs baseline: 3.5230x; 1.0009x over previous
#include <cuda_runtime.h>

// ---------------- problem constants ----------------
#define BB 64
#define SS 129
#define FF 768
#define DD 4
#define KDIM (SS*FF)        // 99072
#define N3 (3*BB)           // 192
#define MOM 0.9f
#define EPSV 1e-6f

// output layout (tuple flattened)
#define XMIX_N (BB*SS*FF)
#define LOSS_OFF XMIX_N
#define NM_OFF (XMIX_N + 1)
#define NV_OFF (NM_OFF + DD*FF)

// ---------------- gram config ----------------
#define KSPLIT 129
#define KCHUNK 768
#define NTILES 24
#define SROW 36
#define BUF_ELEMS (N3*SROW)
#define NPAIR 6
#define PAIRSZ 4096
#define KSLAB (NPAIR*PAIRSZ)   // 24576

// ---------------- device scratch ----------------
__device__ float g_pA1[4][BB*FF];
__device__ float g_pA2[4][BB*FF];
__device__ float g_mu[BB*FF];
__device__ float g_inv[BB*FF];
__device__ float g_nm[DD*FF];
__device__ float g_nsd[DD*FF];
__device__ float g_gpart[KSPLIT*KSLAB];
__device__ float g_part2[8][KSLAB];
__device__ float g_G[N3*N3];
__device__ float g_rowloss[N3];

// ---------------- helpers ----------------
__device__ __forceinline__ unsigned tf32r(float v) {
    unsigned r;
    asm("cvt.rna.tf32.f32 %0, %1;" : "=r"(r) : "f"(v));
    return r;
}

__device__ __forceinline__ void mma_tf32(float* d, const unsigned* a, const unsigned* b) {
    asm volatile("mma.sync.aligned.m16n8k8.row.col.f32.tf32.tf32.f32 "
        "{%0,%1,%2,%3},{%4,%5,%6,%7},{%8,%9},{%0,%1,%2,%3};"
        : "+f"(d[0]), "+f"(d[1]), "+f"(d[2]), "+f"(d[3])
        : "r"(a[0]), "r"(a[1]), "r"(a[2]), "r"(a[3]), "r"(b[0]), "r"(b[1]));
}

// ---------------- stage A1: split-S partial sums -----------------------------
__global__ void stageA1(const float* __restrict__ x) {
    int bf = blockIdx.x;
    int seg = blockIdx.y;
    int b = bf / 3;
    int f = (bf % 3) * 256 + threadIdx.x;
    int s0 = (seg == 0) ? 0 : 33 + 32 * (seg - 1);
    int s1 = 33 + 32 * seg;
    const float* p = x + (size_t)b * KDIM + f;
    float sa = 0.f, sb2 = 0.f, sc = 0.f, sd2 = 0.f;
    int ss = s0;
    for (; ss + 1 < s1; ss += 2) {
        float v0 = p[(size_t)ss * FF];
        float v1 = p[(size_t)(ss + 1) * FF];
        sa += v0; sb2 += v0 * v0;
        sc += v1; sd2 += v1 * v1;
    }
    if (ss < s1) { float v = p[(size_t)ss * FF]; sa += v; sb2 += v * v; }
    int o = b * FF + f;
    g_pA1[seg][o] = sa + sc;
    g_pA2[seg][o] = sb2 + sd2;
}

// ------- stage AB: combine partials + instance stats + domain EMA ------------
// 12 blocks, each covers f-range [blk*64, blk*64+64)
__global__ void stageAB(const float* __restrict__ mean_buf,
                        const float* __restrict__ var_buf,
                        const int* __restrict__ domain,
                        float* __restrict__ out) {
    __shared__ float s1s[64][65];
    __shared__ float s2s[64][65];
    __shared__ int doms[64];
    int tid = threadIdx.x;
    int f0 = blockIdx.x * 64;
    if (tid < 64) doms[tid] = domain[tid];
    #pragma unroll
    for (int i = 0; i < 16; i++) {
        int e = tid + 256 * i;          // 0..4095
        int b = e >> 6, f = e & 63;
        int idx = b * FF + f0 + f;
        float s  = g_pA1[0][idx] + g_pA1[1][idx] + g_pA1[2][idx] + g_pA1[3][idx];
        float s2 = g_pA2[0][idx] + g_pA2[1][idx] + g_pA2[2][idx] + g_pA2[3][idx];
        float mu = s / (float)SS;
        float var = (s2 - (float)SS * mu * mu) / (float)(SS - 1);
        g_mu[idx] = mu;
        g_inv[idx] = rsqrtf(var + EPSV);
        s1s[b][f] = s;
        s2s[b][f] = s2;
    }
    __syncthreads();
    int d = tid >> 6, f = tid & 63;     // 4 x 64 = 256 exactly
    float s1 = 0.f, s2 = 0.f;
    int nb = 0;
    #pragma unroll 8
    for (int b = 0; b < BB; b++) {
        if (doms[b] == d) {
            nb++;
            s1 += s1s[b][f];
            s2 += s2s[b][f];
        }
    }
    float n = (float)nb * (float)SS;
    float mu = s1 / fmaxf(n, 1.f);
    float var = (s2 - n * mu * mu) / fmaxf(n - 1.f, 1.f);
    int idx = d * FF + f0 + f;
    float nm, nv;
    if (nb > 0) {
        nm = MOM * mean_buf[idx] + (1.f - MOM) * mu;
        nv = MOM * var_buf[idx] + (1.f - MOM) * var;
    } else {
        nm = mean_buf[idx];
        nv = var_buf[idx];
    }
    out[NM_OFF + idx] = nm;
    out[NV_OFF + idx] = nv;
    g_nm[idx] = nm;
    g_nsd[idx] = sqrtf(nv + EPSV);
}

// ---------------- fused gram (tf32 mma.sync) + xmix + hg ---------------------
// 512 threads. Loader: thread handles quad q of rows {b, 64+b, 128+b}, b=tid>>3,
// loading x row once (feeds gram row 0-63 AND xmix). MMA: 2 warp groups x 8
// warps; group A -> pairs (0,0)(0,1)(0,2), group B -> (1,1)(1,2)(2,2).
__global__ __launch_bounds__(512, 1)
void gram_tc(const float* __restrict__ x,
             const float* __restrict__ hgn,
             const float* __restrict__ lmda,
             const int* __restrict__ domain,
             const int* __restrict__ drand,
             float* __restrict__ out) {
    extern __shared__ unsigned sbuf[];   // 2 * BUF_ELEMS
    int tid = threadIdx.x;
    int ks = blockIdx.x;
    long kbase = (long)ks * KCHUNK;

    // ---- loader setup ----
    int b = tid >> 3, q = tid & 7;
    const float* px = x   + (size_t)b * KDIM + kbase + q * 4;
    const float* ph = hgn + (size_t)b * KDIM + kbase + q * 4;
    float* outp     = out + (size_t)b * KDIM + kbase + q * 4;
    float lm = lmda[b];
    int dom = domain[b];
    int ds = (dom + drand[b]) & 3;
    int offm  = b * FF + q * 4;
    int offdx = ds * FF + q * 4;
    int offdh = dom * FF + q * 4;
    int soff0 = b * SROW + q * 4;
    int soff1 = (64 + b) * SROW + q * 4;
    int soff2 = (128 + b) * SROW + q * 4;

    // ---- mma setup ----
    int wid = tid >> 5, lane = tid & 31;
    int grp = wid >> 3, wpos = wid & 7;
    int wm = wpos >> 2, wn = wpos & 3;
    int lr = lane >> 2, lc = lane & 3;
    float acc[3][2][2][4];
    #pragma unroll
    for (int pp = 0; pp < 3; pp++)
        #pragma unroll
        for (int mt = 0; mt < 2; mt++)
            #pragma unroll
            for (int nt = 0; nt < 2; nt++)
                #pragma unroll
                for (int r = 0; r < 4; r++) acc[pp][mt][nt][r] = 0.f;

    float4 vx = *(const float4*)px;
    float4 vh = *(const float4*)ph;

    for (int t = 0; t < NTILES; t++) {
        unsigned* bb = sbuf + (t & 1) * BUF_ELEMS;
        int fo = t * 32;
        // xmix from the already-loaded x quad
        float4 mu = *(const float4*)(g_mu  + offm  + fo);
        float4 iv = *(const float4*)(g_inv + offm  + fo);
        float4 nmx = *(const float4*)(g_nm  + offdx + fo);
        float4 sdx = *(const float4*)(g_nsd + offdx + fo);
        float il = 1.f - lm;
        float4 xm;
        xm.x = lm * vx.x + il * fmaf((vx.x - mu.x) * iv.x, sdx.x, nmx.x);
        xm.y = lm * vx.y + il * fmaf((vx.y - mu.y) * iv.y, sdx.y, nmx.y);
        xm.z = lm * vx.z + il * fmaf((vx.z - mu.z) * iv.z, sdx.z, nmx.z);
        xm.w = lm * vx.w + il * fmaf((vx.w - mu.w) * iv.w, sdx.w, nmx.w);
        *(float4*)(outp + fo) = xm;
        // hg
        float4 nmh = *(const float4*)(g_nm  + offdh + fo);
        float4 sdh = *(const float4*)(g_nsd + offdh + fo);
        float4 hg;
        hg.x = fmaf(sdh.x, vh.x, nmh.x);
        hg.y = fmaf(sdh.y, vh.y, nmh.y);
        hg.z = fmaf(sdh.z, vh.z, nmh.z);
        hg.w = fmaf(sdh.w, vh.w, nmh.w);
        // tf32 + STS
        uint4 u0, u1, u2;
        u0.x = tf32r(vx.x); u0.y = tf32r(vx.y); u0.z = tf32r(vx.z); u0.w = tf32r(vx.w);
        u1.x = tf32r(xm.x); u1.y = tf32r(xm.y); u1.z = tf32r(xm.z); u1.w = tf32r(xm.w);
        u2.x = tf32r(hg.x); u2.y = tf32r(hg.y); u2.z = tf32r(hg.z); u2.w = tf32r(hg.w);
        *(uint4*)(&bb[soff0]) = u0;
        *(uint4*)(&bb[soff1]) = u1;
        *(uint4*)(&bb[soff2]) = u2;
        // prefetch next tile
        if (t + 1 < NTILES) {
            vx = *(const float4*)(px + (t + 1) * 32);
            vh = *(const float4*)(ph + (t + 1) * 32);
        }
        __syncthreads();
        const unsigned* S = bb;
        if (grp == 0) {
            #pragma unroll
            for (int kk = 0; kk < 4; kk++) {
                int k0 = kk * 8;
                unsigned af[2][4], bf[3][2][2];
                #pragma unroll
                for (int mt = 0; mt < 2; mt++) {
                    int r0 = wm * 32 + mt * 16 + lr;
                    af[mt][0] = S[r0 * SROW + k0 + lc];
                    af[mt][1] = S[(r0 + 8) * SROW + k0 + lc];
                    af[mt][2] = S[r0 * SROW + k0 + lc + 4];
                    af[mt][3] = S[(r0 + 8) * SROW + k0 + lc + 4];
                }
                #pragma unroll
                for (int g = 0; g < 3; g++)
                    #pragma unroll
                    for (int nt = 0; nt < 2; nt++) {
                        int n0 = g * 64 + wn * 16 + nt * 8 + lr;
                        bf[g][nt][0] = S[n0 * SROW + k0 + lc];
                        bf[g][nt][1] = S[n0 * SROW + k0 + lc + 4];
                    }
                #pragma unroll
                for (int pp = 0; pp < 3; pp++)
                    #pragma unroll
                    for (int mt = 0; mt < 2; mt++)
                        #pragma unroll
                        for (int nt = 0; nt < 2; nt++)
                            mma_tf32(acc[pp][mt][nt], af[mt], bf[pp][nt]);
            }
        } else {
            #pragma unroll
            for (int kk = 0; kk < 4; kk++) {
                int k0 = kk * 8;
                unsigned af[2][2][4], bf[2][2][2];
                #pragma unroll
                for (int ga = 0; ga < 2; ga++)
                    #pragma unroll
                    for (int mt = 0; mt < 2; mt++) {
                        int r0 = (ga + 1) * 64 + wm * 32 + mt * 16 + lr;
                        af[ga][mt][0] = S[r0 * SROW + k0 + lc];
                        af[ga][mt][1] = S[(r0 + 8) * SROW + k0 + lc];
                        af[ga][mt][2] = S[r0 * SROW + k0 + lc + 4];
                        af[ga][mt][3] = S[(r0 + 8) * SROW + k0 + lc + 4];
                    }
                #pragma unroll
                for (int gb = 0; gb < 2; gb++)
                    #pragma unroll
                    for (int nt = 0; nt < 2; nt++) {
                        int n0 = (gb + 1) * 64 + wn * 16 + nt * 8 + lr;
                        bf[gb][nt][0] = S[n0 * SROW + k0 + lc];
                        bf[gb][nt][1] = S[n0 * SROW + k0 + lc + 4];
                    }
                const int PA[3] = {0, 0, 1};
                const int PB[3] = {0, 1, 1};
                #pragma unroll
                for (int pp = 0; pp < 3; pp++)
                    #pragma unroll
                    for (int mt = 0; mt < 2; mt++)
                        #pragma unroll
                        for (int nt = 0; nt < 2; nt++)
                            mma_tf32(acc[pp][mt][nt], af[PA[pp]][mt], bf[PB[pp]][nt]);
            }
        }
    }

    // ---- epilogue: each warp group writes its 3 pair-tiles ----
    float* base = g_gpart + (size_t)ks * KSLAB;
    #pragma unroll
    for (int pp = 0; pp < 3; pp++) {
        int pair = grp * 3 + pp;
        #pragma unroll
        for (int mt = 0; mt < 2; mt++) {
            #pragma unroll
            for (int nt = 0; nt < 2; nt++) {
                int r = wm * 32 + mt * 16 + lr;
                int c = wn * 16 + nt * 8 + lc * 2;
                float* dst = base + pair * PAIRSZ + r * 64 + c;
                *(float2*)dst = make_float2(acc[pp][mt][nt][0], acc[pp][mt][nt][1]);
                *(float2*)(dst + 8 * 64) = make_float2(acc[pp][mt][nt][2], acc[pp][mt][nt][3]);
            }
        }
    }
}

// ---------------- split-K reduction stage 1: 129 -> 8 ------------------------
__global__ void reduceG1() {
    int idx = blockIdx.x * 256 + threadIdx.x;
    int c = blockIdx.y;
    int p0 = c * 16;
    int p1 = (c == 7) ? 129 : p0 + 16;
    const float* src = g_gpart + (size_t)p0 * KSLAB + idx;
    float s0 = 0.f, s1 = 0.f, s2 = 0.f, s3 = 0.f;
    int n = p1 - p0;
    int p = 0;
    for (; p + 3 < n; p += 4) {
        s0 += src[(size_t)p * KSLAB];
        s1 += src[(size_t)(p + 1) * KSLAB];
        s2 += src[(size_t)(p + 2) * KSLAB];
        s3 += src[(size_t)(p + 3) * KSLAB];
    }
    for (; p < n; p++) s0 += src[(size_t)p * KSLAB];
    g_part2[c][idx] = (s0 + s1) + (s2 + s3);
}

// ---------------- stage 2: sum 8 chunks + symmetry mirror --------------------
__global__ void reduceG2() {
    int idx = blockIdx.x * 256 + threadIdx.x;
    if (idx >= N3 * N3) return;
    int i = idx / N3, j = idx % N3;
    int ti = i >> 6, tj = j >> 6, li = i & 63, lj = j & 63;
    int a, b2, la, lb;
    if (ti <= tj) { a = ti; b2 = tj; la = li; lb = lj; }
    else          { a = tj; b2 = ti; la = lj; lb = li; }
    int pair = a * (5 - a) / 2 + b2;
    int o = pair * PAIRSZ + la * 64 + lb;
    float s = 0.f;
    #pragma unroll
    for (int c = 0; c < 8; c++) s += g_part2[c][o];
    g_G[idx] = s;
}

// ---------------- triplet loss: warp per row ---------------------------------
__global__ void lossA(const int* __restrict__ labels) {
    int i = (blockIdx.x * blockDim.x + threadIdx.x) >> 5;
    int lane = threadIdx.x & 31;
    int li = (i < 2 * BB) ? labels[i & 63] : -1;
    float sqi = g_G[i * N3 + i];
    float ap = -1e30f, an = 1e30f;
    #pragma unroll
    for (int jj = 0; jj < 6; jj++) {
        int j = lane + jj * 32;
        int lj = (j < 2 * BB) ? labels[j & 63] : -1;
        float d2 = sqi + g_G[j * N3 + j] - 2.f * g_G[i * N3 + j];
        float dd = sqrtf(fmaxf(d2, 1e-12f));
        if (li == lj) ap = fmaxf(ap, dd);
        else          an = fminf(an, dd);
    }
    #pragma unroll
    for (int o = 16; o > 0; o >>= 1) {
        ap = fmaxf(ap, __shfl_xor_sync(0xFFFFFFFFu, ap, o));
        an = fminf(an, __shfl_xor_sync(0xFFFFFFFFu, an, o));
    }
    if (lane == 0) {
        float z = ap - an;
        g_rowloss[i] = (z > 0.f) ? (z + log1pf(expf(-z))) : log1pf(expf(z));
    }
}

__global__ void lossB(float* __restrict__ out) {
    __shared__ float red[256];
    int t = threadIdx.x;
    red[t] = (t < N3) ? g_rowloss[t] : 0.f;
    __syncthreads();
    for (int st = 128; st > 0; st >>= 1) {
        if (t < st) red[t] += red[t + st];
        __syncthreads();
    }
    if (t == 0) out[LOSS_OFF] = red[0] / (float)N3;
}

// ---------------- launch ------------------------------------------------------
extern "C" void kernel_launch(void* const* d_in, const int* in_sizes, int n_in,
                              void* d_out, int out_size) {
    const float* x        = (const float*)d_in[0];
    const float* lmda     = (const float*)d_in[1];
    const float* mean_buf = (const float*)d_in[2];
    const float* var_buf  = (const float*)d_in[3];
    const float* hgn      = (const float*)d_in[4];
    const int*   labels   = (const int*)d_in[5];
    const int*   domain   = (const int*)d_in[6];
    const int*   d_rand   = (const int*)d_in[7];
    float* out = (float*)d_out;

    int smem_sz = 2 * BUF_ELEMS * (int)sizeof(unsigned);   // 55296
    cudaFuncSetAttribute(gram_tc, cudaFuncAttributeMaxDynamicSharedMemorySize, smem_sz);

    dim3 ga(BB * 3, 4);
    stageA1<<<ga, 256>>>(x);
    stageAB<<<FF / 64, 256>>>(mean_buf, var_buf, domain, out);
    gram_tc<<<KSPLIT, 512, smem_sz>>>(x, hgn, lmda, domain, d_rand, out);
    dim3 gr(KSLAB / 256, 8);
    reduceG1<<<gr, 256>>>();
    reduceG2<<<(N3 * N3 + 255) / 256, 256>>>();
    lossA<<<N3 / 8, 256>>>(labels);
    lossB<<<1, 256>>>(out);
}